// round 1
// baseline (speedup 1.0000x reference)
#include <cuda_runtime.h>

#define D_MODEL 512
#define HIDDEN  2048
#define N_EXP   8
#define NTOK    8192
#define NPAIR   (NTOK * 2)

// ---------------- scratch (static __device__ — no allocs allowed) ----------
__device__ int   g_counts[N_EXP];
__device__ int   g_list[N_EXP][NTOK];          // pair indices per expert
__device__ float g_wpair[NPAIR];               // combine weight per pair
__device__ float g_H[(size_t)NPAIR * HIDDEN];  // ~134 MB
__device__ float g_Y[(size_t)NPAIR * D_MODEL]; // ~33 MB

// ---------------- init: zero routing counts each replay --------------------
__global__ void init_kernel() {
    if (threadIdx.x < N_EXP) g_counts[threadIdx.x] = 0;
}

// ---------------- gating: one warp per token -------------------------------
__global__ void gate_kernel(const float* __restrict__ x,
                            const float* __restrict__ Wg,
                            const float* __restrict__ bg) {
    int t    = blockIdx.x * 8 + threadIdx.y;
    int lane = threadIdx.x;
    const float* xr = x + (size_t)t * D_MODEL;

    float acc[N_EXP];
#pragma unroll
    for (int e = 0; e < N_EXP; e++) acc[e] = 0.f;

    for (int d = lane; d < D_MODEL; d += 32) {
        float xv = xr[d];
        const float* wrow = Wg + d * N_EXP;
#pragma unroll
        for (int e = 0; e < N_EXP; e++) acc[e] += xv * wrow[e];
    }
#pragma unroll
    for (int e = 0; e < N_EXP; e++) {
#pragma unroll
        for (int o = 16; o > 0; o >>= 1)
            acc[e] += __shfl_down_sync(0xffffffffu, acc[e], o);
    }

    if (lane == 0) {
        float s[N_EXP];
#pragma unroll
        for (int e = 0; e < N_EXP; e++) s[e] = acc[e] + bg[e];

        // top-2, jax.lax.top_k tie semantics (lower index first): strict >
        int i0 = 0;
#pragma unroll
        for (int e = 1; e < N_EXP; e++) if (s[e] > s[i0]) i0 = e;
        int i1 = (i0 == 0) ? 1 : 0;
#pragma unroll
        for (int e = 0; e < N_EXP; e++)
            if (e != i0 && e != i1 && s[e] > s[i1]) i1 = e;

        // softmax over [s[i0], s[i1]] with s[i0] >= s[i1]
        float e1 = expf(s[i1] - s[i0]);
        float z  = 1.0f + e1;
        float w0 = 1.0f / z;
        float w1 = e1 / z;

        int p0 = atomicAdd(&g_counts[i0], 1);
        g_list[i0][p0]  = t * 2;
        g_wpair[t * 2]  = w0;
        int p1 = atomicAdd(&g_counts[i1], 1);
        g_list[i1][p1]      = t * 2 + 1;
        g_wpair[t * 2 + 1]  = w1;
    }
}

// ---------------- grouped SGEMM tiles --------------------------------------
#define BM 128
#define BN 128
#define BK 16

// Pass 1: H[pair, 0:2048] = relu(x[tok] @ W1[e] + b1[e])
__global__ __launch_bounds__(256) void ffn1_kernel(
    const float* __restrict__ x, const float* __restrict__ W1,
    const float* __restrict__ b1) {
    int e     = blockIdx.z;
    int count = g_counts[e];
    int m0    = blockIdx.x * BM;
    if (m0 >= count) return;
    int n0    = blockIdx.y * BN;

    __shared__ float As[BK][BM + 4];
    __shared__ float Bs[BK][BN];

    int tid = threadIdx.x;
    int tx  = tid & 15, ty = tid >> 4;

    // A-load assignment: each thread loads rows (ar, ar+64), 4 cols
    int ar = tid >> 2;
    int ac = (tid & 3) * 4;
    const float* arow0;
    const float* arow1;
    {
        int m  = min(m0 + ar, count - 1);
        arow0  = x + (size_t)(g_list[e][m] >> 1) * D_MODEL;
        m      = min(m0 + ar + 64, count - 1);
        arow1  = x + (size_t)(g_list[e][m] >> 1) * D_MODEL;
    }
    const float* Be = W1 + (size_t)e * D_MODEL * HIDDEN;
    int bc = (tid & 31) * 4;
    int br = tid >> 5;

    float acc[8][8];
#pragma unroll
    for (int i = 0; i < 8; i++)
#pragma unroll
        for (int j = 0; j < 8; j++) acc[i][j] = 0.f;

    for (int k0 = 0; k0 < D_MODEL; k0 += BK) {
        float4 va0 = *(const float4*)(arow0 + k0 + ac);
        float4 va1 = *(const float4*)(arow1 + k0 + ac);
        As[ac + 0][ar] = va0.x; As[ac + 1][ar] = va0.y;
        As[ac + 2][ar] = va0.z; As[ac + 3][ar] = va0.w;
        As[ac + 0][ar + 64] = va1.x; As[ac + 1][ar + 64] = va1.y;
        As[ac + 2][ar + 64] = va1.z; As[ac + 3][ar + 64] = va1.w;
#pragma unroll
        for (int kk = 0; kk < BK; kk += 8) {
            float4 vb = *(const float4*)(Be + (size_t)(k0 + br + kk) * HIDDEN + n0 + bc);
            *(float4*)&Bs[br + kk][bc] = vb;
        }
        __syncthreads();
#pragma unroll
        for (int kk = 0; kk < BK; kk++) {
            float a[8], b[8];
            *(float4*)(a)     = *(const float4*)&As[kk][ty * 8];
            *(float4*)(a + 4) = *(const float4*)&As[kk][ty * 8 + 4];
            *(float4*)(b)     = *(const float4*)&Bs[kk][tx * 8];
            *(float4*)(b + 4) = *(const float4*)&Bs[kk][tx * 8 + 4];
#pragma unroll
            for (int i = 0; i < 8; i++)
#pragma unroll
                for (int j = 0; j < 8; j++) acc[i][j] += a[i] * b[j];
        }
        __syncthreads();
    }

#pragma unroll
    for (int i = 0; i < 8; i++) {
        int m = m0 + ty * 8 + i;
        if (m < count) {
            int pair  = g_list[e][m];
            float* yr = g_H + (size_t)pair * HIDDEN + n0 + tx * 8;
#pragma unroll
            for (int j = 0; j < 8; j++) {
                float v = acc[i][j] + b1[e * HIDDEN + n0 + tx * 8 + j];
                yr[j] = fmaxf(v, 0.f);
            }
        }
    }
}

// Pass 2: Y[pair, 0:512] = w_pair * (H[pair] @ W2[e] + b2[e])
__global__ __launch_bounds__(256) void ffn2_kernel(
    const float* __restrict__ W2, const float* __restrict__ b2) {
    int e     = blockIdx.z;
    int count = g_counts[e];
    int m0    = blockIdx.x * BM;
    if (m0 >= count) return;
    int n0    = blockIdx.y * BN;

    __shared__ float As[BK][BM + 4];
    __shared__ float Bs[BK][BN];

    int tid = threadIdx.x;
    int tx  = tid & 15, ty = tid >> 4;

    int ar = tid >> 2;
    int ac = (tid & 3) * 4;
    const float* arow0;
    const float* arow1;
    {
        int m  = min(m0 + ar, count - 1);
        arow0  = g_H + (size_t)g_list[e][m] * HIDDEN;
        m      = min(m0 + ar + 64, count - 1);
        arow1  = g_H + (size_t)g_list[e][m] * HIDDEN;
    }
    const float* Be = W2 + (size_t)e * HIDDEN * D_MODEL;
    int bc = (tid & 31) * 4;
    int br = tid >> 5;

    float acc[8][8];
#pragma unroll
    for (int i = 0; i < 8; i++)
#pragma unroll
        for (int j = 0; j < 8; j++) acc[i][j] = 0.f;

    for (int k0 = 0; k0 < HIDDEN; k0 += BK) {
        float4 va0 = *(const float4*)(arow0 + k0 + ac);
        float4 va1 = *(const float4*)(arow1 + k0 + ac);
        As[ac + 0][ar] = va0.x; As[ac + 1][ar] = va0.y;
        As[ac + 2][ar] = va0.z; As[ac + 3][ar] = va0.w;
        As[ac + 0][ar + 64] = va1.x; As[ac + 1][ar + 64] = va1.y;
        As[ac + 2][ar + 64] = va1.z; As[ac + 3][ar + 64] = va1.w;
#pragma unroll
        for (int kk = 0; kk < BK; kk += 8) {
            float4 vb = *(const float4*)(Be + (size_t)(k0 + br + kk) * D_MODEL + n0 + bc);
            *(float4*)&Bs[br + kk][bc] = vb;
        }
        __syncthreads();
#pragma unroll
        for (int kk = 0; kk < BK; kk++) {
            float a[8], b[8];
            *(float4*)(a)     = *(const float4*)&As[kk][ty * 8];
            *(float4*)(a + 4) = *(const float4*)&As[kk][ty * 8 + 4];
            *(float4*)(b)     = *(const float4*)&Bs[kk][tx * 8];
            *(float4*)(b + 4) = *(const float4*)&Bs[kk][tx * 8 + 4];
#pragma unroll
            for (int i = 0; i < 8; i++)
#pragma unroll
                for (int j = 0; j < 8; j++) acc[i][j] += a[i] * b[j];
        }
        __syncthreads();
    }

#pragma unroll
    for (int i = 0; i < 8; i++) {
        int m = m0 + ty * 8 + i;
        if (m < count) {
            int pair  = g_list[e][m];
            float w   = g_wpair[pair];
            float* yr = g_Y + (size_t)pair * D_MODEL + n0 + tx * 8;
#pragma unroll
            for (int j = 0; j < 8; j++) {
                float v = acc[i][j] + b2[e * D_MODEL + n0 + tx * 8 + j];
                yr[j] = w * v;
            }
        }
    }
}

// ---------------- combine: out[t] = Y[2t] + Y[2t+1] ------------------------
__global__ void combine_kernel(float* __restrict__ out) {
    int i = blockIdx.x * 256 + threadIdx.x;   // over NTOK*128 float4s
    int t = i >> 7, d = i & 127;
    const float4* Y4 = (const float4*)g_Y;
    float4 a = Y4[(size_t)(2 * t) * 128 + d];
    float4 b = Y4[(size_t)(2 * t + 1) * 128 + d];
    float4 o;
    o.x = a.x + b.x; o.y = a.y + b.y; o.z = a.z + b.z; o.w = a.w + b.w;
    ((float4*)out)[i] = o;
}

// ---------------- launch ----------------------------------------------------
extern "C" void kernel_launch(void* const* d_in, const int* in_sizes, int n_in,
                              void* d_out, int out_size) {
    const float* x  = (const float*)d_in[0];
    const float* W1 = (const float*)d_in[1];
    const float* b1 = (const float*)d_in[2];
    const float* W2 = (const float*)d_in[3];
    const float* b2 = (const float*)d_in[4];
    const float* Wg = (const float*)d_in[5];
    const float* bg = (const float*)d_in[6];
    float* out = (float*)d_out;

    init_kernel<<<1, 32>>>();
    gate_kernel<<<NTOK / 8, dim3(32, 8)>>>(x, Wg, bg);
    ffn1_kernel<<<dim3(NTOK / BM, HIDDEN / BN, N_EXP), 256>>>(x, W1, b1);
    ffn2_kernel<<<dim3(NTOK / BM, D_MODEL / BN, N_EXP), 256>>>(W2, b2);
    combine_kernel<<<(NTOK * D_MODEL / 4) / 256, 256>>>(out);
}

// round 3
// speedup vs baseline: 2.7087x; 2.7087x over previous
#include <cuda_runtime.h>
#include <cuda_bf16.h>
#include <cstdint>

#define D_MODEL 512
#define HIDDEN  2048
#define N_EXP   8
#define NTOK    8192
#define NPAIR   (NTOK * 2)

// ---------------- scratch (static __device__ — no allocs allowed) ----------
__device__ int   g_counts[N_EXP];
__device__ int   g_list[N_EXP][NTOK];          // pair indices per expert
__device__ float g_wpair[NPAIR];
__device__ __nv_bfloat16 g_Xh[(size_t)NTOK * D_MODEL];
__device__ __nv_bfloat16 g_Xl[(size_t)NTOK * D_MODEL];
// transposed + bf16-split weights: [e][n][k]
__device__ __nv_bfloat16 g_W1t_h[(size_t)N_EXP * HIDDEN * D_MODEL];
__device__ __nv_bfloat16 g_W1t_l[(size_t)N_EXP * HIDDEN * D_MODEL];
__device__ __nv_bfloat16 g_W2t_h[(size_t)N_EXP * D_MODEL * HIDDEN];
__device__ __nv_bfloat16 g_W2t_l[(size_t)N_EXP * D_MODEL * HIDDEN];
__device__ __nv_bfloat16 g_Hh[(size_t)NPAIR * HIDDEN];
__device__ __nv_bfloat16 g_Hl[(size_t)NPAIR * HIDDEN];
__device__ float g_Y[(size_t)NPAIR * D_MODEL];

// ---------------- PTX helpers (base sm_103 target ONLY: no tcgen05) --------
__device__ __forceinline__ uint32_t smem_u32(const void* p) {
    uint32_t a;
    asm("{ .reg .u64 t; cvta.to.shared.u64 t, %1; cvt.u32.u64 %0, t; }"
        : "=r"(a) : "l"(p));
    return a;
}
#define CP16(dst, src) \
    asm volatile("cp.async.cg.shared.global [%0], [%1], 16;" \
                 :: "r"(dst), "l"(src) : "memory")
#define CP_COMMIT() asm volatile("cp.async.commit_group;" ::: "memory")
#define CP_WAIT0()  asm volatile("cp.async.wait_group 0;" ::: "memory")
#define CP_WAIT1()  asm volatile("cp.async.wait_group 1;" ::: "memory")

#define LDSM4(R, a) \
    asm volatile("ldmatrix.sync.aligned.m8n8.x4.shared.b16 {%0,%1,%2,%3}, [%4];" \
                 : "=r"((R)[0]), "=r"((R)[1]), "=r"((R)[2]), "=r"((R)[3]) : "r"(a))

#define MMA16816(D, A, B0, B1) \
    asm volatile("mma.sync.aligned.m16n8k16.row.col.f32.bf16.bf16.f32 " \
                 "{%0,%1,%2,%3}, {%4,%5,%6,%7}, {%8,%9}, {%0,%1,%2,%3};" \
                 : "+f"((D)[0]), "+f"((D)[1]), "+f"((D)[2]), "+f"((D)[3]) \
                 : "r"((A)[0]), "r"((A)[1]), "r"((A)[2]), "r"((A)[3]), \
                   "r"(B0), "r"(B1))

__device__ __forceinline__ uint32_t swz(uint32_t o) { return o ^ ((o >> 3) & 0x70); }

// bf16 hi/lo split of two floats -> packed bf16x2 words
__device__ __forceinline__ void split2(float a, float b, uint32_t& hi, uint32_t& lo) {
    __nv_bfloat16 ha = __float2bfloat16_rn(a);
    __nv_bfloat16 hb = __float2bfloat16_rn(b);
    __nv_bfloat16 la = __float2bfloat16_rn(a - __bfloat162float(ha));
    __nv_bfloat16 lb = __float2bfloat16_rn(b - __bfloat162float(hb));
    hi = (uint32_t)__bfloat16_as_ushort(ha) | ((uint32_t)__bfloat16_as_ushort(hb) << 16);
    lo = (uint32_t)__bfloat16_as_ushort(la) | ((uint32_t)__bfloat16_as_ushort(lb) << 16);
}

// ---------------- init + gate (unchanged, proven) ---------------------------
__global__ void init_kernel() {
    if (threadIdx.x < N_EXP) g_counts[threadIdx.x] = 0;
}

__global__ void gate_kernel(const float* __restrict__ x,
                            const float* __restrict__ Wg,
                            const float* __restrict__ bg) {
    int t    = blockIdx.x * 8 + threadIdx.y;
    int lane = threadIdx.x;
    const float* xr = x + (size_t)t * D_MODEL;
    float acc[N_EXP];
#pragma unroll
    for (int e = 0; e < N_EXP; e++) acc[e] = 0.f;
    for (int d = lane; d < D_MODEL; d += 32) {
        float xv = xr[d];
        const float* wrow = Wg + d * N_EXP;
#pragma unroll
        for (int e = 0; e < N_EXP; e++) acc[e] += xv * wrow[e];
    }
#pragma unroll
    for (int e = 0; e < N_EXP; e++)
#pragma unroll
        for (int o = 16; o > 0; o >>= 1)
            acc[e] += __shfl_down_sync(0xffffffffu, acc[e], o);
    if (lane == 0) {
        float s[N_EXP];
#pragma unroll
        for (int e = 0; e < N_EXP; e++) s[e] = acc[e] + bg[e];
        int i0 = 0;
#pragma unroll
        for (int e = 1; e < N_EXP; e++) if (s[e] > s[i0]) i0 = e;
        int i1 = (i0 == 0) ? 1 : 0;
#pragma unroll
        for (int e = 0; e < N_EXP; e++)
            if (e != i0 && e != i1 && s[e] > s[i1]) i1 = e;
        float e1 = expf(s[i1] - s[i0]);
        float z  = 1.0f + e1;
        int p0 = atomicAdd(&g_counts[i0], 1);
        g_list[i0][p0] = t * 2;
        g_wpair[t * 2] = 1.0f / z;
        int p1 = atomicAdd(&g_counts[i1], 1);
        g_list[i1][p1]     = t * 2 + 1;
        g_wpair[t * 2 + 1] = e1 / z;
    }
}

// ---------------- input / weight conversion ---------------------------------
__global__ void convert_x(const float* __restrict__ x) {
    int i = blockIdx.x * 256 + threadIdx.x;       // over NTOK*D_MODEL/4
    float4 v = ((const float4*)x)[i];
    uint32_t h0, l0, h1, l1;
    split2(v.x, v.y, h0, l0);
    split2(v.z, v.w, h1, l1);
    ((uint2*)g_Xh)[i] = make_uint2(h0, h1);
    ((uint2*)g_Xl)[i] = make_uint2(l0, l1);
}

// W1 [E][512][2048] -> W1t [E][2048][512] hi/lo
__global__ void convert_w1(const float* __restrict__ W1) {
    __shared__ float t[32][33];
    int e  = blockIdx.z;
    int n0 = blockIdx.x * 32, k0 = blockIdx.y * 32;
    int tx = threadIdx.x, ty = threadIdx.y;
    const float* in = W1 + (size_t)e * D_MODEL * HIDDEN;
#pragma unroll
    for (int j = 0; j < 32; j += 8)
        t[ty + j][tx] = in[(size_t)(k0 + ty + j) * HIDDEN + n0 + tx];
    __syncthreads();
    size_t ob = ((size_t)e * HIDDEN + n0) * D_MODEL + k0;
#pragma unroll
    for (int j = 0; j < 32; j += 8) {
        float v = t[tx][ty + j];
        __nv_bfloat16 h = __float2bfloat16_rn(v);
        g_W1t_h[ob + (size_t)(ty + j) * D_MODEL + tx] = h;
        g_W1t_l[ob + (size_t)(ty + j) * D_MODEL + tx] =
            __float2bfloat16_rn(v - __bfloat162float(h));
    }
}
// W2 [E][2048][512] -> W2t [E][512][2048] hi/lo
__global__ void convert_w2(const float* __restrict__ W2) {
    __shared__ float t[32][33];
    int e  = blockIdx.z;
    int n0 = blockIdx.x * 32, k0 = blockIdx.y * 32;
    int tx = threadIdx.x, ty = threadIdx.y;
    const float* in = W2 + (size_t)e * HIDDEN * D_MODEL;
#pragma unroll
    for (int j = 0; j < 32; j += 8)
        t[ty + j][tx] = in[(size_t)(k0 + ty + j) * D_MODEL + n0 + tx];
    __syncthreads();
    size_t ob = ((size_t)e * D_MODEL + n0) * HIDDEN + k0;
#pragma unroll
    for (int j = 0; j < 32; j += 8) {
        float v = t[tx][ty + j];
        __nv_bfloat16 h = __float2bfloat16_rn(v);
        g_W2t_h[ob + (size_t)(ty + j) * HIDDEN + tx] = h;
        g_W2t_l[ob + (size_t)(ty + j) * HIDDEN + tx] =
            __float2bfloat16_rn(v - __bfloat162float(h));
    }
}

// ---------------- grouped split-bf16 HMMA GEMM ------------------------------
// CTA tile 128x128, BK=64 bf16, double-buffered cp.async.
// SMEM: [0,512) pair list; A bufs @1024 (2x16KB); B bufs @33792 (2x16KB).
#define SMEM_SZ (1024 + 65536)

template <int PHASE>
__global__ __launch_bounds__(256, 2) void ffn_mma(const float* __restrict__ bias) {
    constexpr int KSEG = (PHASE == 1) ? D_MODEL : HIDDEN;
    constexpr int NCS  = KSEG / 64;      // chunks per segment
    constexpr int NC   = 3 * NCS;        // total K chunks (3-term split)
    constexpr int NOUT = (PHASE == 1) ? HIDDEN : D_MODEL;

    int e     = blockIdx.z;
    int count = g_counts[e];
    int m0    = blockIdx.x * 128;
    if (m0 >= count) return;
    int n0    = blockIdx.y * 128;

    extern __shared__ char smem[];
    uint32_t sb = smem_u32(smem);
    int tid = threadIdx.x, lane = tid & 31, wid = tid >> 5;

    int* sp = (int*)smem;
    if (tid < 128) sp[tid] = g_list[e][min(m0 + tid, count - 1)];
    __syncthreads();

    const __nv_bfloat16* Ah = (PHASE == 1) ? g_Xh : g_Hh;
    const __nv_bfloat16* Al = (PHASE == 1) ? g_Xl : g_Hl;
    const __nv_bfloat16* Bh =
        ((PHASE == 1) ? g_W1t_h : g_W2t_h) + (size_t)e * (HIDDEN * D_MODEL);
    const __nv_bfloat16* Bl =
        ((PHASE == 1) ? g_W1t_l : g_W2t_l) + (size_t)e * (HIDDEN * D_MODEL);

    // per-thread cp.async slots: 4 A-chunks + 4 B-chunks of 16B
    uint32_t dA[4], dB[4];
    int aoff[4], boff[4];
#pragma unroll
    for (int t = 0; t < 4; t++) {
        int id = tid + t * 256;
        int r = id >> 3, g = id & 7;
        uint32_t so = swz((uint32_t)(r * 128 + g * 16));
        dA[t] = sb + 1024 + so;
        dB[t] = sb + 1024 + 32768 + so;
        int arow = (PHASE == 1) ? (sp[r] >> 1) : sp[r];
        aoff[t] = arow * KSEG + g * 8;
        boff[t] = (n0 + r) * KSEG + g * 8;
    }

    // warp tile: 64m x 32n at (wm, wn); 2x4 warp grid
    int wm = (wid & 1) * 64, wn = (wid >> 1) * 32;
    int mat = lane >> 3, lrow = lane & 7;
    uint32_t arp[4], brp[2];
#pragma unroll
    for (int i = 0; i < 4; i++)
        arp[i] = (uint32_t)((wm + i * 16 + (mat & 1) * 8 + lrow) * 128);
#pragma unroll
    for (int j = 0; j < 2; j++)
        brp[j] = (uint32_t)((wn + j * 16 + (mat >> 1) * 8 + lrow) * 128);
    uint32_t acb = (uint32_t)((mat >> 1) * 16);
    uint32_t bcb = (uint32_t)((mat & 1) * 16);

    float acc[4][4][4];
#pragma unroll
    for (int i = 0; i < 4; i++)
#pragma unroll
        for (int j = 0; j < 4; j++)
#pragma unroll
            for (int q = 0; q < 4; q++) acc[i][j][q] = 0.f;

    // prologue: chunk 0 (segment 0: Ah x Bh)
#pragma unroll
    for (int t = 0; t < 4; t++) CP16(dA[t], Ah + aoff[t]);
#pragma unroll
    for (int t = 0; t < 4; t++) CP16(dB[t], Bh + boff[t]);
    CP_COMMIT();

#pragma unroll 1
    for (int c = 0; c < NC; c++) {
        if (c + 1 < NC) {
            int cn  = c + 1;
            int seg = (cn >= 2 * NCS) ? 2 : ((cn >= NCS) ? 1 : 0);
            int kk  = (cn - seg * NCS) * 64;
            const __nv_bfloat16* As = ((seg == 1) ? Al : Ah) + kk;
            const __nv_bfloat16* Bs = ((seg == 2) ? Bl : Bh) + kk;
            uint32_t bo = (uint32_t)(cn & 1) * 16384u;
#pragma unroll
            for (int t = 0; t < 4; t++) CP16(dA[t] + bo, As + aoff[t]);
#pragma unroll
            for (int t = 0; t < 4; t++) CP16(dB[t] + bo, Bs + boff[t]);
            CP_COMMIT();
            CP_WAIT1();
        } else {
            CP_WAIT0();
        }
        __syncthreads();

        uint32_t sA = sb + 1024 + (uint32_t)(c & 1) * 16384u;
        uint32_t sB = sA + 32768u;
#pragma unroll
        for (int ks = 0; ks < 4; ks++) {
            uint32_t a[4][4], b[2][4];
#pragma unroll
            for (int i = 0; i < 4; i++)
                LDSM4(a[i], sA + swz(arp[i] + (uint32_t)ks * 32 + acb));
#pragma unroll
            for (int j = 0; j < 2; j++)
                LDSM4(b[j], sB + swz(brp[j] + (uint32_t)ks * 32 + bcb));
#pragma unroll
            for (int i = 0; i < 4; i++)
#pragma unroll
                for (int j = 0; j < 4; j++)
                    MMA16816(acc[i][j], a[i], b[j >> 1][(j & 1) * 2],
                             b[j >> 1][(j & 1) * 2 + 1]);
        }
        __syncthreads();
    }

    // epilogue
    const float* bse = bias + e * NOUT + n0;
    int tig = lane & 3, gid = lane >> 2;
#pragma unroll
    for (int i = 0; i < 4; i++) {
        int r1 = wm + i * 16 + gid;
#pragma unroll
        for (int j = 0; j < 4; j++) {
            int nl = wn + j * 8 + tig * 2;
            float2 bb = *(const float2*)(bse + nl);
            if (PHASE == 1) {
                if (m0 + r1 < count) {
                    int pr = sp[r1];
                    uint32_t h, l;
                    split2(fmaxf(acc[i][j][0] + bb.x, 0.f),
                           fmaxf(acc[i][j][1] + bb.y, 0.f), h, l);
                    *(uint32_t*)(g_Hh + (size_t)pr * HIDDEN + n0 + nl) = h;
                    *(uint32_t*)(g_Hl + (size_t)pr * HIDDEN + n0 + nl) = l;
                }
                if (m0 + r1 + 8 < count) {
                    int pr = sp[r1 + 8];
                    uint32_t h, l;
                    split2(fmaxf(acc[i][j][2] + bb.x, 0.f),
                           fmaxf(acc[i][j][3] + bb.y, 0.f), h, l);
                    *(uint32_t*)(g_Hh + (size_t)pr * HIDDEN + n0 + nl) = h;
                    *(uint32_t*)(g_Hl + (size_t)pr * HIDDEN + n0 + nl) = l;
                }
            } else {
                if (m0 + r1 < count) {
                    int pr = sp[r1];
                    float w = g_wpair[pr];
                    float2 o;
                    o.x = w * (acc[i][j][0] + bb.x);
                    o.y = w * (acc[i][j][1] + bb.y);
                    *(float2*)(g_Y + (size_t)pr * D_MODEL + n0 + nl) = o;
                }
                if (m0 + r1 + 8 < count) {
                    int pr = sp[r1 + 8];
                    float w = g_wpair[pr];
                    float2 o;
                    o.x = w * (acc[i][j][2] + bb.x);
                    o.y = w * (acc[i][j][3] + bb.y);
                    *(float2*)(g_Y + (size_t)pr * D_MODEL + n0 + nl) = o;
                }
            }
        }
    }
}

// ---------------- combine: out[t] = Y[2t] + Y[2t+1] ------------------------
__global__ void combine_kernel(float* __restrict__ out) {
    int i = blockIdx.x * 256 + threadIdx.x;
    int t = i >> 7, d = i & 127;
    const float4* Y4 = (const float4*)g_Y;
    float4 a = Y4[(size_t)(2 * t) * 128 + d];
    float4 b = Y4[(size_t)(2 * t + 1) * 128 + d];
    float4 o;
    o.x = a.x + b.x; o.y = a.y + b.y; o.z = a.z + b.z; o.w = a.w + b.w;
    ((float4*)out)[i] = o;
}

// ---------------- launch ----------------------------------------------------
extern "C" void kernel_launch(void* const* d_in, const int* in_sizes, int n_in,
                              void* d_out, int out_size) {
    const float* x  = (const float*)d_in[0];
    const float* W1 = (const float*)d_in[1];
    const float* b1 = (const float*)d_in[2];
    const float* W2 = (const float*)d_in[3];
    const float* b2 = (const float*)d_in[4];
    const float* Wg = (const float*)d_in[5];
    const float* bg = (const float*)d_in[6];
    float* out = (float*)d_out;

    cudaFuncSetAttribute(ffn_mma<1>, cudaFuncAttributeMaxDynamicSharedMemorySize, SMEM_SZ);
    cudaFuncSetAttribute(ffn_mma<2>, cudaFuncAttributeMaxDynamicSharedMemorySize, SMEM_SZ);

    init_kernel<<<1, 32>>>();
    gate_kernel<<<NTOK / 8, dim3(32, 8)>>>(x, Wg, bg);
    convert_x<<<(NTOK * D_MODEL / 4) / 256, 256>>>(x);
    convert_w1<<<dim3(HIDDEN / 32, D_MODEL / 32, N_EXP), dim3(32, 8)>>>(W1);
    convert_w2<<<dim3(D_MODEL / 32, HIDDEN / 32, N_EXP), dim3(32, 8)>>>(W2);
    ffn_mma<1><<<dim3(NTOK / 128, HIDDEN / 128, N_EXP), 256, SMEM_SZ>>>(b1);
    ffn_mma<2><<<dim3(NTOK / 128, D_MODEL / 128, N_EXP), 256, SMEM_SZ>>>(b2);
    combine_kernel<<<(NTOK * D_MODEL / 4) / 256, 256>>>(out);
}